// round 16
// baseline (speedup 1.0000x reference)
#include <cuda_runtime.h>

#define N_NODES 40000
#define N_EDGES 640000
#define ND 128
#define ED 64
#define IN_DIM 320   // 2*ND + ED
#define NT 4         // edge tiles per block
#define EPW 8        // edges per warp
#define EWARPS 12    // warps per edge block
#define ETHREADS (EWARPS * 32)
#define TILE_E (EWARPS * EPW)
#define WBUF 2560    // per-warp buffer floats: ef 512 | P/hs 1024 | Q 1024

typedef unsigned long long u64;

__device__ __forceinline__ u64 pack2(float lo, float hi) {
    u64 r;
    asm("mov.b64 %0, {%1, %2};" : "=l"(r) : "f"(lo), "f"(hi));
    return r;
}
__device__ __forceinline__ void unpack2(u64 v, float& lo, float& hi) {
    asm("mov.b64 {%0, %1}, %2;" : "=f"(lo), "=f"(hi) : "l"(v));
}
__device__ __forceinline__ void ffma2(u64& d, u64 a, u64 b) {
    asm("fma.rn.f32x2 %0, %1, %2, %0;" : "+l"(d) : "l"(a), "l"(b));
}
__device__ __forceinline__ void red_add_v4(float* p, float a, float b, float c,
                                           float d) {
    asm volatile("red.global.add.v4.f32 [%0], {%1, %2, %3, %4};"
                 :: "l"(p), "f"(a), "f"(b), "f"(c), "f"(d) : "memory");
}
__device__ __forceinline__ void cp_async16(unsigned int dst, const void* src) {
    asm volatile("cp.async.cg.shared.global [%0], [%1], 16;"
                 :: "r"(dst), "l"(src) : "memory");
}
#define CP_COMMIT() asm volatile("cp.async.commit_group;" ::: "memory")
#define CP_WAIT(n)  asm volatile("cp.async.wait_group %0;" :: "n"(n) : "memory")
__device__ __forceinline__ float sigmoidf_(float x) {
    return 1.0f / (1.0f + __expf(-x));
}
// Output permutation: thread lane owns logical outputs {4l..4l+3}; physical
// slots arranged so load#1 (lane*16B) = {4l,4l+1}, load#2 (+512B) = {4l+2,4l+3}.
__device__ __forceinline__ int physo(int o) {
    return ((o & 2) << 5) | ((o >> 2) << 1) | (o & 1);
}

// Device-global scratch (no allocation).
__device__ float g_agg[(size_t)N_NODES * ND];
__device__ float g_P[(size_t)N_NODES * ND];     // nf @ W1a + b1
__device__ float g_Q[(size_t)N_NODES * ND];     // nf @ W1b
__device__ u64 g_w1p[(IN_DIM / 2) * ND];        // [kp][phys(o)]
__device__ u64 g_w2p[(ND / 2) * ND];
__device__ u64 g_gruT[(ND / 2) * 768];          // [kp][ih:384 | hh:384], permuted

__global__ void zero_agg_kernel() {
    size_t total = (size_t)N_NODES * ND / 4;
    float4 z = make_float4(0.f, 0.f, 0.f, 0.f);
    for (size_t i = (size_t)blockIdx.x * blockDim.x + threadIdx.x; i < total;
         i += (size_t)gridDim.x * blockDim.x)
        ((float4*)g_agg)[i] = z;
}

__global__ void prep_kernel(const float* __restrict__ W1,
                            const float* __restrict__ W2,
                            const float* __restrict__ W_ih,
                            const float* __restrict__ W_hh) {
    int i = blockIdx.x * blockDim.x + threadIdx.x;
    if (i < (IN_DIM / 2) * ND) {
        int kp = i >> 7, o = i & 127;
        g_w1p[(kp << 7) + physo(o)] =
            pack2(W1[(2 * kp) * ND + o], W1[(2 * kp + 1) * ND + o]);
    }
    if (i < (ND / 2) * ND) {
        int kp = i >> 7, o = i & 127;
        g_w2p[(kp << 7) + physo(o)] =
            pack2(W2[(2 * kp) * ND + o], W2[(2 * kp + 1) * ND + o]);
    }
    if (i < (ND / 2) * 768) {
        int kp = i / 768, r = i % 768;
        const float* W = (r < 384) ? W_ih : W_hh;
        int of = (r < 384) ? r : r - 384;       // gate*128 + o
        int g = of >> 7, o = of & 127;
        int slot = ((r < 384) ? 0 : 384) + (g << 7) + physo(o);
        g_gruT[kp * 768 + slot] = pack2(W[of * ND + 2 * kp], W[of * ND + 2 * kp + 1]);
    }
}

// P = nf @ W1a + b1 ; Q = nf @ W1b  (per node), 64 nodes/block.
// Two phases: stage W1a in smem -> compute/store P; restage W1b -> Q.
// Block weight LDG traffic: 4 MB -> 128 KB.
__global__ __launch_bounds__(512) void pq_kernel(const float* __restrict__ nf,
                                                 const float* __restrict__ b1) {
    extern __shared__ __align__(16) unsigned char psm_[];
    float* sX = (float*)psm_;              // 64 x 128 (32 KB)
    u64* sW = (u64*)(sX + 64 * ND);        // 64 kp x 128 (64 KB)

    const int t = threadIdx.x, w = t >> 5, lane = t & 31, o0 = lane * 4;
    const int n0 = blockIdx.x * 64;

    #pragma unroll
    for (int i = 0; i < 4; i++) {
        int n = w * 4 + i;
        ((float4*)(sX + n * ND))[lane] =
            ((const float4*)(nf + (size_t)(n0 + n) * ND))[lane];
    }

    #pragma unroll
    for (int phase = 0; phase < 2; phase++) {
        __syncthreads();
        // stage this phase's 64-kp weight block (4096 ulonglong2)
        {
            const ulonglong2* src = (const ulonglong2*)g_w1p + phase * 4096;
            ulonglong2* dst = (ulonglong2*)sW;
            #pragma unroll
            for (int c = 0; c < 8; c++) dst[t + 512 * c] = src[t + 512 * c];
        }
        __syncthreads();

        u64 acc[16];
        if (phase == 0) {
            float4 b1v = *(const float4*)(b1 + o0);
            float bb[4] = {b1v.x, b1v.y, b1v.z, b1v.w};
            #pragma unroll
            for (int i = 0; i < 4; i++)
                #pragma unroll
                for (int j = 0; j < 4; j++) acc[4 * i + j] = pack2(bb[j], 0.f);
        } else {
            #pragma unroll
            for (int i = 0; i < 16; i++) acc[i] = 0ull;
        }

        #pragma unroll 2
        for (int kp2 = 0; kp2 < 32; kp2++) {
            const u64* wp = sW + (size_t)(2 * kp2) * ND;
            ulonglong2 wA = *(const ulonglong2*)(wp + 2 * lane);
            ulonglong2 wB = *(const ulonglong2*)(wp + 64 + 2 * lane);
            ulonglong2 wC = *(const ulonglong2*)(wp + ND + 2 * lane);
            ulonglong2 wD = *(const ulonglong2*)(wp + ND + 64 + 2 * lane);
            #pragma unroll
            for (int i = 0; i < 4; i++) {
                int n = w * 4 + i;
                ulonglong2 x = *(const ulonglong2*)(sX + n * ND + 4 * kp2);
                u64* a = acc + 4 * i;
                ffma2(a[0], wA.x, x.x); ffma2(a[1], wA.y, x.x);
                ffma2(a[2], wB.x, x.x); ffma2(a[3], wB.y, x.x);
                ffma2(a[0], wC.x, x.y); ffma2(a[1], wC.y, x.y);
                ffma2(a[2], wD.x, x.y); ffma2(a[3], wD.y, x.y);
            }
        }
        float* dst = phase == 0 ? g_P : g_Q;
        #pragma unroll
        for (int i = 0; i < 4; i++) {
            int n = n0 + w * 4 + i;
            float4 pv;
            float lo, hi;
            unpack2(acc[4 * i + 0], lo, hi); pv.x = lo + hi;
            unpack2(acc[4 * i + 1], lo, hi); pv.y = lo + hi;
            unpack2(acc[4 * i + 2], lo, hi); pv.z = lo + hi;
            unpack2(acc[4 * i + 3], lo, hi); pv.w = lo + hi;
            *(float4*)(dst + (size_t)n * ND + o0) = pv;
        }
    }
}

// Edge kernel (R10 configuration: 12 warps x 8 edges, cp.async staging).
__global__ __launch_bounds__(ETHREADS, 1) void edge_kernel(
    const int* __restrict__ ei, const float* __restrict__ ef,
    const float* __restrict__ ln_g, const float* __restrict__ ln_b,
    const float* __restrict__ b2, const float* __restrict__ gate_w,
    const float* __restrict__ gate_b)
{
    extern __shared__ __align__(16) unsigned char smem_raw[];
    u64* sW1c = (u64*)smem_raw;                 // 32 kp x 128  (32 KB)
    u64* sW2  = sW1c + 32 * ND;                 // 64 kp x 128  (64 KB)
    float* buf = (float*)(sW2 + 64 * ND);       // 12 warps x 2560 f (120 KB)

    const int t = threadIdx.x, w = t >> 5, lane = t & 31, o0 = lane * 4;

    // cooperative weight load (layout already permuted in global).
    // W1c starts at u64 offset 128*ND = 16384 -> ulonglong2 offset 8192.
    {
        const ulonglong2* s1 = (const ulonglong2*)g_w1p;
        ulonglong2* d1 = (ulonglong2*)sW1c;
        for (int i = t; i < 2048; i += ETHREADS) d1[i] = s1[8192 + i];
        const ulonglong2* s2 = (const ulonglong2*)g_w2p;
        ulonglong2* d2 = (ulonglong2*)sW2;
        for (int i = t; i < 4096; i += ETHREADS) d2[i] = s2[i];
    }
    const float gw0 = gate_w[lane], gw1 = gate_w[lane + 32], gb = gate_b[0];
    __syncthreads();

    float* bufw = buf + w * WBUF;
    float* efw  = bufw;             // [0,512): 8 edges x 64
    float* sPh  = bufw + 512;       // [512,1536): P stage, then hs overlay
    float* sQ   = bufw + 1536;      // [1536,2560): Q stage
    const unsigned int bufb = (unsigned int)__cvta_generic_to_shared(bufw);

    for (int it = 0; it < NT; it++) {
        const int e_base = (blockIdx.x * NT + it) * TILE_E + w * EPW;
        if (e_base >= N_EDGES) continue;

        int sReg = 0, dReg = 0;
        if (lane < EPW) {
            sReg = ei[e_base + lane];
            dReg = ei[N_EDGES + e_base + lane];
        }
        // --- stage ef rows (group A): 8 rows x 256B; 2 rows per pass ---
        #pragma unroll
        for (int pass = 0; pass < 4; pass++) {
            int e = pass * 2 + (lane >> 4);
            int idx = lane & 15;
            cp_async16(bufb + (unsigned)(e * 256 + idx * 16),
                       ef + (size_t)(e_base + e) * ED + idx * 4);
        }
        CP_COMMIT();
        // --- stage P[src], Q[dst] rows (group B): 16 rows x 512B ---
        #pragma unroll
        for (int e = 0; e < EPW; e++) {
            int s = __shfl_sync(0xffffffffu, sReg, e);
            int d = __shfl_sync(0xffffffffu, dReg, e);
            cp_async16(bufb + (unsigned)((512 + e * ND) * 4 + lane * 16),
                       g_P + (size_t)s * ND + lane * 4);
            cp_async16(bufb + (unsigned)((1536 + e * ND) * 4 + lane * 16),
                       g_Q + (size_t)d * ND + lane * 4);
        }
        CP_COMMIT();

        CP_WAIT(1);        // ef ready; P/Q still in flight
        __syncwarp();

        // ---- R GEMM (K=64) ----
        u64 acc[32];
        #pragma unroll
        for (int i = 0; i < 32; i++) acc[i] = 0ull;
        #pragma unroll 2
        for (int kp2 = 0; kp2 < 16; kp2++) {
            const u64* wp = sW1c + (2 * kp2) * ND;
            ulonglong2 wA = *(const ulonglong2*)(wp + 2 * lane);
            ulonglong2 wB = *(const ulonglong2*)(wp + 64 + 2 * lane);
            ulonglong2 wC = *(const ulonglong2*)(wp + ND + 2 * lane);
            ulonglong2 wD = *(const ulonglong2*)(wp + ND + 64 + 2 * lane);
            #pragma unroll
            for (int e = 0; e < EPW; e++) {
                ulonglong2 x = *(const ulonglong2*)(efw + e * ED + 4 * kp2);
                u64* a = acc + 4 * e;
                ffma2(a[0], wA.x, x.x); ffma2(a[1], wA.y, x.x);
                ffma2(a[2], wB.x, x.x); ffma2(a[3], wB.y, x.x);
                ffma2(a[0], wC.x, x.y); ffma2(a[1], wC.y, x.y);
                ffma2(a[2], wD.x, x.y); ffma2(a[3], wD.y, x.y);
            }
        }

        // ---- sigmoid gate per edge (reads efw) ----
        float gv[EPW];
        #pragma unroll
        for (int e = 0; e < EPW; e++) {
            float p = efw[e * ED + lane] * gw0 + efw[e * ED + lane + 32] * gw1;
            #pragma unroll
            for (int off = 16; off; off >>= 1)
                p += __shfl_xor_sync(0xffffffffu, p, off);
            gv[e] = sigmoidf_(p + gb);
        }

        CP_WAIT(0);        // P/Q staged
        __syncwarp();

        // ---- P + Q + R, LayerNorm, ReLU -> hs (overlays P stage) ----
        {
            const float4 lgv = ((const float4*)ln_g)[lane];
            const float4 lbv = ((const float4*)ln_b)[lane];
            #pragma unroll
            for (int e = 0; e < EPW; e++) {
                float4 Pv = *(const float4*)(sPh + e * ND + o0);
                float4 Qv = *(const float4*)(sQ + e * ND + o0);
                float v[4];
                float lo, hi;
                unpack2(acc[4 * e + 0], lo, hi); v[0] = lo + hi + Pv.x + Qv.x;
                unpack2(acc[4 * e + 1], lo, hi); v[1] = lo + hi + Pv.y + Qv.y;
                unpack2(acc[4 * e + 2], lo, hi); v[2] = lo + hi + Pv.z + Qv.z;
                unpack2(acc[4 * e + 3], lo, hi); v[3] = lo + hi + Pv.w + Qv.w;
                float sm = v[0] + v[1] + v[2] + v[3];
                float sq = v[0] * v[0] + v[1] * v[1] + v[2] * v[2] + v[3] * v[3];
                #pragma unroll
                for (int off = 16; off; off >>= 1) {
                    sm += __shfl_xor_sync(0xffffffffu, sm, off);
                    sq += __shfl_xor_sync(0xffffffffu, sq, off);
                }
                float mu  = sm * (1.0f / ND);
                float var = sq * (1.0f / ND) - mu * mu;
                float inv = rsqrtf(var + 1e-5f);
                float4 hv;
                hv.x = fmaxf((v[0] - mu) * inv * lgv.x + lbv.x, 0.f);
                hv.y = fmaxf((v[1] - mu) * inv * lgv.y + lbv.y, 0.f);
                hv.z = fmaxf((v[2] - mu) * inv * lgv.z + lbv.z, 0.f);
                hv.w = fmaxf((v[3] - mu) * inv * lgv.w + lbv.w, 0.f);
                *(float4*)(sPh + e * ND + o0) = hv;
            }
        }
        __syncwarp();

        // ---- layer 2 GEMM (K=128) over hs ----
        #pragma unroll
        for (int i = 0; i < 32; i++) acc[i] = 0ull;
        #pragma unroll 2
        for (int kp2 = 0; kp2 < 32; kp2++) {
            const u64* wp = sW2 + (2 * kp2) * ND;
            ulonglong2 wA = *(const ulonglong2*)(wp + 2 * lane);
            ulonglong2 wB = *(const ulonglong2*)(wp + 64 + 2 * lane);
            ulonglong2 wC = *(const ulonglong2*)(wp + ND + 2 * lane);
            ulonglong2 wD = *(const ulonglong2*)(wp + ND + 64 + 2 * lane);
            #pragma unroll
            for (int e = 0; e < EPW; e++) {
                ulonglong2 x = *(const ulonglong2*)(sPh + e * ND + 4 * kp2);
                u64* a = acc + 4 * e;
                ffma2(a[0], wA.x, x.x); ffma2(a[1], wA.y, x.x);
                ffma2(a[2], wB.x, x.x); ffma2(a[3], wB.y, x.x);
                ffma2(a[0], wC.x, x.y); ffma2(a[1], wC.y, x.y);
                ffma2(a[2], wD.x, x.y); ffma2(a[3], wD.y, x.y);
            }
        }

        // ---- bias + gate + vectorized scatter-add ----
        {
            const float4 b2v = ((const float4*)b2)[lane];
            #pragma unroll
            for (int e = 0; e < EPW; e++) {
                int d = __shfl_sync(0xffffffffu, dReg, e);
                float* dp = g_agg + (size_t)d * ND + o0;
                float lo, hi, m0, m1, m2, m3;
                unpack2(acc[4 * e + 0], lo, hi); m0 = (lo + hi + b2v.x) * gv[e];
                unpack2(acc[4 * e + 1], lo, hi); m1 = (lo + hi + b2v.y) * gv[e];
                unpack2(acc[4 * e + 2], lo, hi); m2 = (lo + hi + b2v.z) * gv[e];
                unpack2(acc[4 * e + 3], lo, hi); m3 = (lo + hi + b2v.w) * gv[e];
                red_add_v4(dp, m0, m1, m2, m3);
            }
        }
        __syncwarp();
    }
}

// GRU with per-gate smem weight staging (R15 version, committed win).
__global__ __launch_bounds__(512) void gru_kernel(
    const float* __restrict__ nf, const float* __restrict__ b_ih,
    const float* __restrict__ b_hh, float* __restrict__ out)
{
    extern __shared__ __align__(16) unsigned char gsm_[];
    u64* sW = (u64*)gsm_;                        // [kp][ih:128 | hh:128]
    float* sAf = (float*)(sW + 64 * 256);        // 64 x 128
    float* sXf = sAf + 64 * ND;                  // 64 x 128

    const int t = threadIdx.x, w = t >> 5, lane = t & 31, o0 = lane * 4;
    const int n0 = blockIdx.x * 64;

    #pragma unroll
    for (int i = 0; i < 4; i++) {
        int n = w * 4 + i;
        ((float4*)(sAf + n * ND))[lane] =
            ((const float4*)(g_agg + (size_t)(n0 + n) * ND))[lane];
        ((float4*)(sXf + n * ND))[lane] =
            ((const float4*)(nf + (size_t)(n0 + n) * ND))[lane];
    }

    float rv[16], zv[16];

    for (int g = 0; g < 3; g++) {
        __syncthreads();
        // stage gate-g weights: 8192 ulonglong2, 16 per thread
        {
            ulonglong2* dst = (ulonglong2*)sW;
            #pragma unroll
            for (int c = 0; c < 16; c++) {
                int j = t + 512 * c;
                int kp = j >> 7, r2 = j & 127;
                int rr = 2 * r2;
                int src = kp * 768 + ((rr < 128) ? (g * 128 + rr)
                                                 : (384 + g * 128 + rr - 128));
                dst[j] = *(const ulonglong2*)(g_gruT + src);
            }
        }
        __syncthreads();

        u64 gi[16], gh[16];
        {
            float4 biv = *(const float4*)(b_ih + g * ND + o0);
            float4 bhv = *(const float4*)(b_hh + g * ND + o0);
            float bi[4] = {biv.x, biv.y, biv.z, biv.w};
            float bh[4] = {bhv.x, bhv.y, bhv.z, bhv.w};
            #pragma unroll
            for (int i = 0; i < 4; i++)
                #pragma unroll
                for (int j = 0; j < 4; j++) {
                    gi[4 * i + j] = pack2(bi[j], 0.f);
                    gh[4 * i + j] = pack2(bh[j], 0.f);
                }
        }
        #pragma unroll 2
        for (int kp2 = 0; kp2 < 32; kp2++) {
            const u64* base0 = sW + (size_t)(2 * kp2) * 256;
            const u64* base1 = base0 + 256;
            ulonglong2 iA = *(const ulonglong2*)(base0 + 2 * lane);
            ulonglong2 iB = *(const ulonglong2*)(base0 + 64 + 2 * lane);
            ulonglong2 iC = *(const ulonglong2*)(base1 + 2 * lane);
            ulonglong2 iD = *(const ulonglong2*)(base1 + 64 + 2 * lane);
            ulonglong2 hA = *(const ulonglong2*)(base0 + 128 + 2 * lane);
            ulonglong2 hB = *(const ulonglong2*)(base0 + 128 + 64 + 2 * lane);
            ulonglong2 hC = *(const ulonglong2*)(base1 + 128 + 2 * lane);
            ulonglong2 hD = *(const ulonglong2*)(base1 + 128 + 64 + 2 * lane);
            #pragma unroll
            for (int i = 0; i < 4; i++) {
                int n = w * 4 + i;
                ulonglong2 xa = *(const ulonglong2*)(sAf + n * ND + 4 * kp2);
                ulonglong2 xx = *(const ulonglong2*)(sXf + n * ND + 4 * kp2);
                u64* pi = gi + 4 * i;
                u64* ph = gh + 4 * i;
                ffma2(pi[0], iA.x, xa.x); ffma2(pi[1], iA.y, xa.x);
                ffma2(pi[2], iB.x, xa.x); ffma2(pi[3], iB.y, xa.x);
                ffma2(pi[0], iC.x, xa.y); ffma2(pi[1], iC.y, xa.y);
                ffma2(pi[2], iD.x, xa.y); ffma2(pi[3], iD.y, xa.y);
                ffma2(ph[0], hA.x, xx.x); ffma2(ph[1], hA.y, xx.x);
                ffma2(ph[2], hB.x, xx.x); ffma2(ph[3], hB.y, xx.x);
                ffma2(ph[0], hC.x, xx.y); ffma2(ph[1], hC.y, xx.y);
                ffma2(ph[2], hD.x, xx.y); ffma2(ph[3], hD.y, xx.y);
            }
        }
        #pragma unroll
        for (int i = 0; i < 4; i++) {
            int n = w * 4 + i;
            #pragma unroll
            for (int j = 0; j < 4; j++) {
                float il, ih, hl, hh;
                unpack2(gi[4 * i + j], il, ih);
                unpack2(gh[4 * i + j], hl, hh);
                float giv = il + ih, ghv = hl + hh;
                if (g == 0) {
                    rv[4 * i + j] = sigmoidf_(giv + ghv);
                } else if (g == 1) {
                    zv[4 * i + j] = sigmoidf_(giv + ghv);
                } else {
                    float nn = tanhf(giv + rv[4 * i + j] * ghv);
                    float x = sXf[n * ND + o0 + j];
                    float z = zv[4 * i + j];
                    rv[4 * i + j] = (1.0f - z) * nn + z * x;
                }
            }
        }
    }
    #pragma unroll
    for (int i = 0; i < 4; i++) {
        int n = n0 + w * 4 + i;
        float4 ov = make_float4(rv[4 * i], rv[4 * i + 1], rv[4 * i + 2], rv[4 * i + 3]);
        *(float4*)(out + (size_t)n * ND + o0) = ov;
    }
}

#define EDGE_SMEM (32 * 128 * 8 + 64 * 128 * 8 + EWARPS * WBUF * 4)
#define GRU_SMEM (64 * 256 * 8 + 2 * 64 * ND * 4)
#define PQ_SMEM (64 * ND * 4 + 64 * 128 * 8)
#define EDGE_TILES ((N_EDGES + TILE_E - 1) / TILE_E)
#define EDGE_BLOCKS ((EDGE_TILES + NT - 1) / NT)

extern "C" void kernel_launch(void* const* d_in, const int* in_sizes, int n_in,
                              void* d_out, int out_size) {
    const float* nf     = (const float*)d_in[0];
    const int*   ei     = (const int*)d_in[1];
    const float* ef     = (const float*)d_in[2];
    const float* W1     = (const float*)d_in[3];
    const float* b1     = (const float*)d_in[4];
    const float* ln_g   = (const float*)d_in[5];
    const float* ln_b   = (const float*)d_in[6];
    const float* W2     = (const float*)d_in[7];
    const float* b2     = (const float*)d_in[8];
    const float* gate_w = (const float*)d_in[9];
    const float* gate_b = (const float*)d_in[10];
    const float* W_ih   = (const float*)d_in[11];
    const float* b_ih   = (const float*)d_in[12];
    const float* W_hh   = (const float*)d_in[13];
    const float* b_hh   = (const float*)d_in[14];
    float* out = (float*)d_out;

    cudaFuncSetAttribute(edge_kernel, cudaFuncAttributeMaxDynamicSharedMemorySize,
                         EDGE_SMEM);
    cudaFuncSetAttribute(gru_kernel, cudaFuncAttributeMaxDynamicSharedMemorySize,
                         GRU_SMEM);
    cudaFuncSetAttribute(pq_kernel, cudaFuncAttributeMaxDynamicSharedMemorySize,
                         PQ_SMEM);

    zero_agg_kernel<<<592, 256>>>();
    prep_kernel<<<192, 256>>>(W1, W2, W_ih, W_hh);
    pq_kernel<<<N_NODES / 64, 512, PQ_SMEM>>>(nf, b1);
    edge_kernel<<<EDGE_BLOCKS, ETHREADS, EDGE_SMEM>>>(
        ei, ef, ln_g, ln_b, b2, gate_w, gate_b);
    gru_kernel<<<N_NODES / 64, 512, GRU_SMEM>>>(nf, b_ih, b_hh, out);
}

// round 17
// speedup vs baseline: 1.0653x; 1.0653x over previous
#include <cuda_runtime.h>

#define N_NODES 40000
#define N_EDGES 640000
#define ND 128
#define ED 64
#define IN_DIM 320   // 2*ND + ED
#define EPW 8        // edges per warp
#define EWARPS 12    // warps per edge block
#define ETHREADS (EWARPS * 32)
#define TILE_E (EWARPS * EPW)    // 96
#define N_ETILES ((N_EDGES + TILE_E - 1) / TILE_E)
#define EGRID 148
#define WBUF 2560    // per-warp buffer floats: ef 512 | P/hs 1024 | Q 1024

typedef unsigned long long u64;

__device__ __forceinline__ u64 pack2(float lo, float hi) {
    u64 r;
    asm("mov.b64 %0, {%1, %2};" : "=l"(r) : "f"(lo), "f"(hi));
    return r;
}
__device__ __forceinline__ void unpack2(u64 v, float& lo, float& hi) {
    asm("mov.b64 {%0, %1}, %2;" : "=f"(lo), "=f"(hi) : "l"(v));
}
__device__ __forceinline__ void ffma2(u64& d, u64 a, u64 b) {
    asm("fma.rn.f32x2 %0, %1, %2, %0;" : "+l"(d) : "l"(a), "l"(b));
}
__device__ __forceinline__ void red_add_v4(float* p, float a, float b, float c,
                                           float d) {
    asm volatile("red.global.add.v4.f32 [%0], {%1, %2, %3, %4};"
                 :: "l"(p), "f"(a), "f"(b), "f"(c), "f"(d) : "memory");
}
__device__ __forceinline__ void cp_async16(unsigned int dst, const void* src) {
    asm volatile("cp.async.cg.shared.global [%0], [%1], 16;"
                 :: "r"(dst), "l"(src) : "memory");
}
#define CP_COMMIT() asm volatile("cp.async.commit_group;" ::: "memory")
#define CP_WAIT(n)  asm volatile("cp.async.wait_group %0;" :: "n"(n) : "memory")
__device__ __forceinline__ float sigmoidf_(float x) {
    return 1.0f / (1.0f + __expf(-x));
}
// Output permutation: thread lane owns logical outputs {4l..4l+3}; physical
// slots arranged so load#1 (lane*16B) = {4l,4l+1}, load#2 (+512B) = {4l+2,4l+3}.
__device__ __forceinline__ int physo(int o) {
    return ((o & 2) << 5) | ((o >> 2) << 1) | (o & 1);
}

// Device-global scratch (no allocation).
__device__ float g_agg[(size_t)N_NODES * ND];
__device__ float g_P[(size_t)N_NODES * ND];     // nf @ W1a + b1
__device__ float g_Q[(size_t)N_NODES * ND];     // nf @ W1b
__device__ u64 g_w1p[(IN_DIM / 2) * ND];        // [kp][phys(o)]
__device__ u64 g_w2p[(ND / 2) * ND];
__device__ u64 g_gruT[(ND / 2) * 768];          // [kp][ih:384 | hh:384], permuted

__global__ void prep_kernel(const float* __restrict__ W1,
                            const float* __restrict__ W2,
                            const float* __restrict__ W_ih,
                            const float* __restrict__ W_hh) {
    int i = blockIdx.x * blockDim.x + threadIdx.x;
    if (i < (IN_DIM / 2) * ND) {
        int kp = i >> 7, o = i & 127;
        g_w1p[(kp << 7) + physo(o)] =
            pack2(W1[(2 * kp) * ND + o], W1[(2 * kp + 1) * ND + o]);
    }
    if (i < (ND / 2) * ND) {
        int kp = i >> 7, o = i & 127;
        g_w2p[(kp << 7) + physo(o)] =
            pack2(W2[(2 * kp) * ND + o], W2[(2 * kp + 1) * ND + o]);
    }
    if (i < (ND / 2) * 768) {
        int kp = i / 768, r = i % 768;
        const float* W = (r < 384) ? W_ih : W_hh;
        int of = (r < 384) ? r : r - 384;       // gate*128 + o
        int g = of >> 7, o = of & 127;
        int slot = ((r < 384) ? 0 : 384) + (g << 7) + physo(o);
        g_gruT[kp * 768 + slot] = pack2(W[of * ND + 2 * kp], W[of * ND + 2 * kp + 1]);
    }
}

// P = nf @ W1a + b1 ; Q = nf @ W1b  (per node), 64 nodes/block.
// Also zeroes this block's 64 g_agg rows (replaces the zero kernel).
__global__ __launch_bounds__(512) void pq_kernel(const float* __restrict__ nf,
                                                 const float* __restrict__ b1) {
    __shared__ __align__(16) float sX[64][ND];
    const int t = threadIdx.x, w = t >> 5, lane = t & 31, o0 = lane * 4;
    const int n0 = blockIdx.x * 64;

    const float4 z4 = make_float4(0.f, 0.f, 0.f, 0.f);
    #pragma unroll
    for (int i = 0; i < 4; i++) {
        int n = w * 4 + i;
        ((float4*)sX[n])[lane] = ((const float4*)(nf + (size_t)(n0 + n) * ND))[lane];
        ((float4*)(g_agg + (size_t)(n0 + n) * ND))[lane] = z4;
    }
    __syncwarp();

    u64 aP[16], aQ[16];
    {
        float4 b1v = *(const float4*)(b1 + o0);
        float bb[4] = {b1v.x, b1v.y, b1v.z, b1v.w};
        #pragma unroll
        for (int i = 0; i < 4; i++)
            #pragma unroll
            for (int j = 0; j < 4; j++) {
                aP[4 * i + j] = pack2(bb[j], 0.f);
                aQ[4 * i + j] = 0ull;
            }
    }

    #pragma unroll 2
    for (int kp2 = 0; kp2 < 32; kp2++) {
        const u64* wp = g_w1p + (size_t)(2 * kp2) * ND;
        const u64* wq = g_w1p + (size_t)(64 + 2 * kp2) * ND;
        ulonglong2 pA = *(const ulonglong2*)(wp + 2 * lane);
        ulonglong2 pB = *(const ulonglong2*)(wp + 64 + 2 * lane);
        ulonglong2 pC = *(const ulonglong2*)(wp + ND + 2 * lane);
        ulonglong2 pD = *(const ulonglong2*)(wp + ND + 64 + 2 * lane);
        ulonglong2 qA = *(const ulonglong2*)(wq + 2 * lane);
        ulonglong2 qB = *(const ulonglong2*)(wq + 64 + 2 * lane);
        ulonglong2 qC = *(const ulonglong2*)(wq + ND + 2 * lane);
        ulonglong2 qD = *(const ulonglong2*)(wq + ND + 64 + 2 * lane);
        #pragma unroll
        for (int i = 0; i < 4; i++) {
            int n = w * 4 + i;
            ulonglong2 x = *(const ulonglong2*)&sX[n][4 * kp2];
            u64* p = aP + 4 * i;
            u64* q = aQ + 4 * i;
            ffma2(p[0], pA.x, x.x); ffma2(p[1], pA.y, x.x);
            ffma2(p[2], pB.x, x.x); ffma2(p[3], pB.y, x.x);
            ffma2(p[0], pC.x, x.y); ffma2(p[1], pC.y, x.y);
            ffma2(p[2], pD.x, x.y); ffma2(p[3], pD.y, x.y);
            ffma2(q[0], qA.x, x.x); ffma2(q[1], qA.y, x.x);
            ffma2(q[2], qB.x, x.x); ffma2(q[3], qB.y, x.x);
            ffma2(q[0], qC.x, x.y); ffma2(q[1], qC.y, x.y);
            ffma2(q[2], qD.x, x.y); ffma2(q[3], qD.y, x.y);
        }
    }
    #pragma unroll
    for (int i = 0; i < 4; i++) {
        int n = n0 + w * 4 + i;
        float4 pv, qv;
        float lo, hi;
        unpack2(aP[4 * i + 0], lo, hi); pv.x = lo + hi;
        unpack2(aP[4 * i + 1], lo, hi); pv.y = lo + hi;
        unpack2(aP[4 * i + 2], lo, hi); pv.z = lo + hi;
        unpack2(aP[4 * i + 3], lo, hi); pv.w = lo + hi;
        unpack2(aQ[4 * i + 0], lo, hi); qv.x = lo + hi;
        unpack2(aQ[4 * i + 1], lo, hi); qv.y = lo + hi;
        unpack2(aQ[4 * i + 2], lo, hi); qv.z = lo + hi;
        unpack2(aQ[4 * i + 3], lo, hi); qv.w = lo + hi;
        *(float4*)(g_P + (size_t)n * ND + o0) = pv;
        *(float4*)(g_Q + (size_t)n * ND + o0) = qv;
    }
}

// Persistent edge kernel: 148 blocks, tile-stride loop; weights filled once
// per SM instead of once per 384-edge block.
__global__ __launch_bounds__(ETHREADS, 1) void edge_kernel(
    const int* __restrict__ ei, const float* __restrict__ ef,
    const float* __restrict__ ln_g, const float* __restrict__ ln_b,
    const float* __restrict__ b2, const float* __restrict__ gate_w,
    const float* __restrict__ gate_b)
{
    extern __shared__ __align__(16) unsigned char smem_raw[];
    u64* sW1c = (u64*)smem_raw;                 // 32 kp x 128  (32 KB)
    u64* sW2  = sW1c + 32 * ND;                 // 64 kp x 128  (64 KB)
    float* buf = (float*)(sW2 + 64 * ND);       // 12 warps x 2560 f (120 KB)

    const int t = threadIdx.x, w = t >> 5, lane = t & 31, o0 = lane * 4;

    // one-time cooperative weight load (layout already permuted in global).
    // W1c starts at u64 offset 128*ND = 16384 -> ulonglong2 offset 8192.
    {
        const ulonglong2* s1 = (const ulonglong2*)g_w1p;
        ulonglong2* d1 = (ulonglong2*)sW1c;
        for (int i = t; i < 2048; i += ETHREADS) d1[i] = s1[8192 + i];
        const ulonglong2* s2 = (const ulonglong2*)g_w2p;
        ulonglong2* d2 = (ulonglong2*)sW2;
        for (int i = t; i < 4096; i += ETHREADS) d2[i] = s2[i];
    }
    const float gw0 = gate_w[lane], gw1 = gate_w[lane + 32], gb = gate_b[0];
    const float4 lgv = ((const float4*)ln_g)[lane];
    const float4 lbv = ((const float4*)ln_b)[lane];
    const float4 b2v = ((const float4*)b2)[lane];
    __syncthreads();

    float* bufw = buf + w * WBUF;
    float* efw  = bufw;             // [0,512): 8 edges x 64
    float* sPh  = bufw + 512;       // [512,1536): P stage, then hs overlay
    float* sQ   = bufw + 1536;      // [1536,2560): Q stage
    const unsigned int bufb = (unsigned int)__cvta_generic_to_shared(bufw);

    for (int tile = blockIdx.x; tile < N_ETILES; tile += gridDim.x) {
        const int e_base = tile * TILE_E + w * EPW;
        if (e_base >= N_EDGES) continue;

        int sReg = 0, dReg = 0;
        if (lane < EPW) {
            sReg = ei[e_base + lane];
            dReg = ei[N_EDGES + e_base + lane];
        }
        // --- stage ef rows (group A): 8 rows x 256B; 2 rows per pass ---
        #pragma unroll
        for (int pass = 0; pass < 4; pass++) {
            int e = pass * 2 + (lane >> 4);
            int idx = lane & 15;
            cp_async16(bufb + (unsigned)(e * 256 + idx * 16),
                       ef + (size_t)(e_base + e) * ED + idx * 4);
        }
        CP_COMMIT();
        // --- stage P[src], Q[dst] rows (group B): 16 rows x 512B ---
        #pragma unroll
        for (int e = 0; e < EPW; e++) {
            int s = __shfl_sync(0xffffffffu, sReg, e);
            int d = __shfl_sync(0xffffffffu, dReg, e);
            cp_async16(bufb + (unsigned)((512 + e * ND) * 4 + lane * 16),
                       g_P + (size_t)s * ND + lane * 4);
            cp_async16(bufb + (unsigned)((1536 + e * ND) * 4 + lane * 16),
                       g_Q + (size_t)d * ND + lane * 4);
        }
        CP_COMMIT();

        CP_WAIT(1);        // ef ready; P/Q still in flight
        __syncwarp();

        // ---- R GEMM (K=64) ----
        u64 acc[32];
        #pragma unroll
        for (int i = 0; i < 32; i++) acc[i] = 0ull;
        #pragma unroll 2
        for (int kp2 = 0; kp2 < 16; kp2++) {
            const u64* wp = sW1c + (2 * kp2) * ND;
            ulonglong2 wA = *(const ulonglong2*)(wp + 2 * lane);
            ulonglong2 wB = *(const ulonglong2*)(wp + 64 + 2 * lane);
            ulonglong2 wC = *(const ulonglong2*)(wp + ND + 2 * lane);
            ulonglong2 wD = *(const ulonglong2*)(wp + ND + 64 + 2 * lane);
            #pragma unroll
            for (int e = 0; e < EPW; e++) {
                ulonglong2 x = *(const ulonglong2*)(efw + e * ED + 4 * kp2);
                u64* a = acc + 4 * e;
                ffma2(a[0], wA.x, x.x); ffma2(a[1], wA.y, x.x);
                ffma2(a[2], wB.x, x.x); ffma2(a[3], wB.y, x.x);
                ffma2(a[0], wC.x, x.y); ffma2(a[1], wC.y, x.y);
                ffma2(a[2], wD.x, x.y); ffma2(a[3], wD.y, x.y);
            }
        }

        // ---- sigmoid gate per edge (reads efw) ----
        float gv[EPW];
        #pragma unroll
        for (int e = 0; e < EPW; e++) {
            float p = efw[e * ED + lane] * gw0 + efw[e * ED + lane + 32] * gw1;
            #pragma unroll
            for (int off = 16; off; off >>= 1)
                p += __shfl_xor_sync(0xffffffffu, p, off);
            gv[e] = sigmoidf_(p + gb);
        }

        CP_WAIT(0);        // P/Q staged
        __syncwarp();

        // ---- P + Q + R, LayerNorm, ReLU -> hs (overlays P stage) ----
        #pragma unroll
        for (int e = 0; e < EPW; e++) {
            float4 Pv = *(const float4*)(sPh + e * ND + o0);
            float4 Qv = *(const float4*)(sQ + e * ND + o0);
            float v[4];
            float lo, hi;
            unpack2(acc[4 * e + 0], lo, hi); v[0] = lo + hi + Pv.x + Qv.x;
            unpack2(acc[4 * e + 1], lo, hi); v[1] = lo + hi + Pv.y + Qv.y;
            unpack2(acc[4 * e + 2], lo, hi); v[2] = lo + hi + Pv.z + Qv.z;
            unpack2(acc[4 * e + 3], lo, hi); v[3] = lo + hi + Pv.w + Qv.w;
            float sm = v[0] + v[1] + v[2] + v[3];
            float sq = v[0] * v[0] + v[1] * v[1] + v[2] * v[2] + v[3] * v[3];
            #pragma unroll
            for (int off = 16; off; off >>= 1) {
                sm += __shfl_xor_sync(0xffffffffu, sm, off);
                sq += __shfl_xor_sync(0xffffffffu, sq, off);
            }
            float mu  = sm * (1.0f / ND);
            float var = sq * (1.0f / ND) - mu * mu;
            float inv = rsqrtf(var + 1e-5f);
            float4 hv;
            hv.x = fmaxf((v[0] - mu) * inv * lgv.x + lbv.x, 0.f);
            hv.y = fmaxf((v[1] - mu) * inv * lgv.y + lbv.y, 0.f);
            hv.z = fmaxf((v[2] - mu) * inv * lgv.z + lbv.z, 0.f);
            hv.w = fmaxf((v[3] - mu) * inv * lgv.w + lbv.w, 0.f);
            *(float4*)(sPh + e * ND + o0) = hv;
        }
        __syncwarp();

        // ---- layer 2 GEMM (K=128) over hs ----
        #pragma unroll
        for (int i = 0; i < 32; i++) acc[i] = 0ull;
        #pragma unroll 2
        for (int kp2 = 0; kp2 < 32; kp2++) {
            const u64* wp = sW2 + (2 * kp2) * ND;
            ulonglong2 wA = *(const ulonglong2*)(wp + 2 * lane);
            ulonglong2 wB = *(const ulonglong2*)(wp + 64 + 2 * lane);
            ulonglong2 wC = *(const ulonglong2*)(wp + ND + 2 * lane);
            ulonglong2 wD = *(const ulonglong2*)(wp + ND + 64 + 2 * lane);
            #pragma unroll
            for (int e = 0; e < EPW; e++) {
                ulonglong2 x = *(const ulonglong2*)(sPh + e * ND + 4 * kp2);
                u64* a = acc + 4 * e;
                ffma2(a[0], wA.x, x.x); ffma2(a[1], wA.y, x.x);
                ffma2(a[2], wB.x, x.x); ffma2(a[3], wB.y, x.x);
                ffma2(a[0], wC.x, x.y); ffma2(a[1], wC.y, x.y);
                ffma2(a[2], wD.x, x.y); ffma2(a[3], wD.y, x.y);
            }
        }

        // ---- bias + gate + vectorized scatter-add ----
        #pragma unroll
        for (int e = 0; e < EPW; e++) {
            int d = __shfl_sync(0xffffffffu, dReg, e);
            float* dp = g_agg + (size_t)d * ND + o0;
            float lo, hi, m0, m1, m2, m3;
            unpack2(acc[4 * e + 0], lo, hi); m0 = (lo + hi + b2v.x) * gv[e];
            unpack2(acc[4 * e + 1], lo, hi); m1 = (lo + hi + b2v.y) * gv[e];
            unpack2(acc[4 * e + 2], lo, hi); m2 = (lo + hi + b2v.z) * gv[e];
            unpack2(acc[4 * e + 3], lo, hi); m3 = (lo + hi + b2v.w) * gv[e];
            red_add_v4(dp, m0, m1, m2, m3);
        }
        __syncwarp();
    }
}

// GRU with per-gate smem weight staging (R15 version, committed win).
__global__ __launch_bounds__(512) void gru_kernel(
    const float* __restrict__ nf, const float* __restrict__ b_ih,
    const float* __restrict__ b_hh, float* __restrict__ out)
{
    extern __shared__ __align__(16) unsigned char gsm_[];
    u64* sW = (u64*)gsm_;                        // [kp][ih:128 | hh:128]
    float* sAf = (float*)(sW + 64 * 256);        // 64 x 128
    float* sXf = sAf + 64 * ND;                  // 64 x 128

    const int t = threadIdx.x, w = t >> 5, lane = t & 31, o0 = lane * 4;
    const int n0 = blockIdx.x * 64;

    #pragma unroll
    for (int i = 0; i < 4; i++) {
        int n = w * 4 + i;
        ((float4*)(sAf + n * ND))[lane] =
            ((const float4*)(g_agg + (size_t)(n0 + n) * ND))[lane];
        ((float4*)(sXf + n * ND))[lane] =
            ((const float4*)(nf + (size_t)(n0 + n) * ND))[lane];
    }

    float rv[16], zv[16];

    for (int g = 0; g < 3; g++) {
        __syncthreads();
        // stage gate-g weights: 8192 ulonglong2, 16 per thread
        {
            ulonglong2* dst = (ulonglong2*)sW;
            #pragma unroll
            for (int c = 0; c < 16; c++) {
                int j = t + 512 * c;
                int kp = j >> 7, r2 = j & 127;
                int rr = 2 * r2;
                int src = kp * 768 + ((rr < 128) ? (g * 128 + rr)
                                                 : (384 + g * 128 + rr - 128));
                dst[j] = *(const ulonglong2*)(g_gruT + src);
            }
        }
        __syncthreads();

        u64 gi[16], gh[16];
        {
            float4 biv = *(const float4*)(b_ih + g * ND + o0);
            float4 bhv = *(const float4*)(b_hh + g * ND + o0);
            float bi[4] = {biv.x, biv.y, biv.z, biv.w};
            float bh[4] = {bhv.x, bhv.y, bhv.z, bhv.w};
            #pragma unroll
            for (int i = 0; i < 4; i++)
                #pragma unroll
                for (int j = 0; j < 4; j++) {
                    gi[4 * i + j] = pack2(bi[j], 0.f);
                    gh[4 * i + j] = pack2(bh[j], 0.f);
                }
        }
        #pragma unroll 2
        for (int kp2 = 0; kp2 < 32; kp2++) {
            const u64* base0 = sW + (size_t)(2 * kp2) * 256;
            const u64* base1 = base0 + 256;
            ulonglong2 iA = *(const ulonglong2*)(base0 + 2 * lane);
            ulonglong2 iB = *(const ulonglong2*)(base0 + 64 + 2 * lane);
            ulonglong2 iC = *(const ulonglong2*)(base1 + 2 * lane);
            ulonglong2 iD = *(const ulonglong2*)(base1 + 64 + 2 * lane);
            ulonglong2 hA = *(const ulonglong2*)(base0 + 128 + 2 * lane);
            ulonglong2 hB = *(const ulonglong2*)(base0 + 128 + 64 + 2 * lane);
            ulonglong2 hC = *(const ulonglong2*)(base1 + 128 + 2 * lane);
            ulonglong2 hD = *(const ulonglong2*)(base1 + 128 + 64 + 2 * lane);
            #pragma unroll
            for (int i = 0; i < 4; i++) {
                int n = w * 4 + i;
                ulonglong2 xa = *(const ulonglong2*)(sAf + n * ND + 4 * kp2);
                ulonglong2 xx = *(const ulonglong2*)(sXf + n * ND + 4 * kp2);
                u64* pi = gi + 4 * i;
                u64* ph = gh + 4 * i;
                ffma2(pi[0], iA.x, xa.x); ffma2(pi[1], iA.y, xa.x);
                ffma2(pi[2], iB.x, xa.x); ffma2(pi[3], iB.y, xa.x);
                ffma2(pi[0], iC.x, xa.y); ffma2(pi[1], iC.y, xa.y);
                ffma2(pi[2], iD.x, xa.y); ffma2(pi[3], iD.y, xa.y);
                ffma2(ph[0], hA.x, xx.x); ffma2(ph[1], hA.y, xx.x);
                ffma2(ph[2], hB.x, xx.x); ffma2(ph[3], hB.y, xx.x);
                ffma2(ph[0], hC.x, xx.y); ffma2(ph[1], hC.y, xx.y);
                ffma2(ph[2], hD.x, xx.y); ffma2(ph[3], hD.y, xx.y);
            }
        }
        #pragma unroll
        for (int i = 0; i < 4; i++) {
            int n = w * 4 + i;
            #pragma unroll
            for (int j = 0; j < 4; j++) {
                float il, ih, hl, hh;
                unpack2(gi[4 * i + j], il, ih);
                unpack2(gh[4 * i + j], hl, hh);
                float giv = il + ih, ghv = hl + hh;
                if (g == 0) {
                    rv[4 * i + j] = sigmoidf_(giv + ghv);
                } else if (g == 1) {
                    zv[4 * i + j] = sigmoidf_(giv + ghv);
                } else {
                    float nn = tanhf(giv + rv[4 * i + j] * ghv);
                    float x = sXf[n * ND + o0 + j];
                    float z = zv[4 * i + j];
                    rv[4 * i + j] = (1.0f - z) * nn + z * x;
                }
            }
        }
    }
    #pragma unroll
    for (int i = 0; i < 4; i++) {
        int n = n0 + w * 4 + i;
        float4 ov = make_float4(rv[4 * i], rv[4 * i + 1], rv[4 * i + 2], rv[4 * i + 3]);
        *(float4*)(out + (size_t)n * ND + o0) = ov;
    }
}

#define EDGE_SMEM (32 * 128 * 8 + 64 * 128 * 8 + EWARPS * WBUF * 4)
#define GRU_SMEM (64 * 256 * 8 + 2 * 64 * ND * 4)

extern "C" void kernel_launch(void* const* d_in, const int* in_sizes, int n_in,
                              void* d_out, int out_size) {
    const float* nf     = (const float*)d_in[0];
    const int*   ei     = (const int*)d_in[1];
    const float* ef     = (const float*)d_in[2];
    const float* W1     = (const float*)d_in[3];
    const float* b1     = (const float*)d_in[4];
    const float* ln_g   = (const float*)d_in[5];
    const float* ln_b   = (const float*)d_in[6];
    const float* W2     = (const float*)d_in[7];
    const float* b2     = (const float*)d_in[8];
    const float* gate_w = (const float*)d_in[9];
    const float* gate_b = (const float*)d_in[10];
    const float* W_ih   = (const float*)d_in[11];
    const float* b_ih   = (const float*)d_in[12];
    const float* W_hh   = (const float*)d_in[13];
    const float* b_hh   = (const float*)d_in[14];
    float* out = (float*)d_out;

    cudaFuncSetAttribute(edge_kernel, cudaFuncAttributeMaxDynamicSharedMemorySize,
                         EDGE_SMEM);
    cudaFuncSetAttribute(gru_kernel, cudaFuncAttributeMaxDynamicSharedMemorySize,
                         GRU_SMEM);

    prep_kernel<<<192, 256>>>(W1, W2, W_ih, W_hh);
    pq_kernel<<<N_NODES / 64, 512>>>(nf, b1);
    edge_kernel<<<EGRID, ETHREADS, EDGE_SMEM>>>(
        ei, ef, ln_g, ln_b, b2, gate_w, gate_b);
    gru_kernel<<<N_NODES / 64, 512, GRU_SMEM>>>(nf, b_ih, b_hh, out);
}